// round 10
// baseline (speedup 1.0000x reference)
#include <cuda_runtime.h>
#include <cuda_bf16.h>
#include <cstdint>

// Problem constants (fixed by the reference setup_inputs)
constexpr int T_STEPS = 2048;
constexpr int BATCH   = 8192;
constexpr int CHUNK   = 32;                  // timesteps per pipeline stage
constexpr int NCHUNK  = T_STEPS / CHUNK;     // 64
constexpr int STAGES  = 3;                   // x staging ring depth
constexpr int EPB     = 32;                  // elements per block
constexpr int TPB     = 96;                  // w0: hidden n0+loads, w1: hidden n1+loads, w2: output
constexpr int HALF    = CHUNK / 2;           // steps loaded per hidden warp per chunk

// Izhikevich params (regular spiking)
#define IZH_A   0.02f
#define IZH_B   0.2f
#define IZH_C   (-65.0f)
#define IZH_D   8.0f
#define IZH_VTH 30.0f

// Constant-folded head of the spike-path polynomial, stepwise in fp32 so each
// intermediate rounds exactly as the runtime ops did in the proven R6 kernel:
//   t1 = 0.04f*C; t2 = t1*C; t3 = t2 + 5.0f*C; K4 = t3 + 140.0f
constexpr float KP1 = 0.04f * IZH_C;
constexpr float KP2 = KP1 * IZH_C;
constexpr float KP3 = KP2 + 5.0f * IZH_C;    // 5.0f*C = -325.0f exact
constexpr float KP4 = KP3 + 140.0f;

__device__ __forceinline__ void cp_async16(void* smem_dst, const void* gmem_src) {
    uint32_t s = (uint32_t)__cvta_generic_to_shared(smem_dst);
    asm volatile("cp.async.cg.shared.global [%0], [%1], 16;\n" :: "r"(s), "l"(gmem_src) : "memory");
}
__device__ __forceinline__ void cp_commit() {
    asm volatile("cp.async.commit_group;\n" ::: "memory");
}
__device__ __forceinline__ void cp_wait1() {
    asm volatile("cp.async.wait_group 1;\n" ::: "memory");
}

// The reference polynomial, FROZEN source expression (bit-exact vs reference).
__device__ __forceinline__ float izh_poly(float v, float u, float I) {
    return v + (0.04f * v * v + 5.0f * v + 140.0f - u + I);
}

// Cheap spike-path poly: poly(C, u, I) with the constant head folded.
// Adds only -> no contraction risk; value bit-identical to izh_poly(C, u, I).
__device__ __forceinline__ float izh_poly_C(float u, float I) {
    return IZH_C + ((KP4 - u) + I);
}

__global__ __launch_bounds__(TPB) void snn_izh_spec32b_kernel(
    const float4* __restrict__ xs,     // [T, B] float4 (F_IN = 4)
    const float*  __restrict__ W_in,   // [2,4]
    const float*  __restrict__ b_in,   // [2]
    const float*  __restrict__ W_out,  // [1,2]
    const float*  __restrict__ b_out,  // [1]
    float*        __restrict__ out)    // [T, B]
{
    // x staging ring: 3 stages x 32 steps x 32 lanes x float4 = 48 KB
    __shared__ float4 xring[STAGES][CHUNK][EPB];
    // packed spike double-buffer: [buf][neuron][group-of-4-steps][lane] = 16 KB
    __shared__ float4 zbuf[2][2][CHUNK / 4][EPB];

    const int wid  = threadIdx.x >> 5;
    const int lane = threadIdx.x & 31;
    const int elem = blockIdx.x * EPB + lane;

    if (wid < 2) {
        // ───── HIDDEN warp: owns neuron n, loads half of each chunk ─────
        const int n = wid;
        const float w0 = W_in[n * 4 + 0];
        const float w1 = W_in[n * 4 + 1];
        const float w2 = W_in[n * 4 + 2];
        const float w3 = W_in[n * 4 + 3];
        const float bi = b_in[n];

        const float4* xp = xs + elem;          // stride BATCH between timesteps
        const int soff = n * HALF;             // this warp's half of every chunk

        // prologue: stage s holds chunk s; issue stages 0..1 (2 groups)
        #pragma unroll
        for (int s = 0; s < STAGES - 1; s++) {
            #pragma unroll
            for (int k = 0; k < HALF; k++)
                cp_async16(&xring[s][soff + k][lane],
                           xp + (size_t)(s * CHUNK + soff + k) * BATCH);
            cp_commit();
        }

        // speculative state: vn = pre-reset v of prev step, up = u' (pre +D), p = prev spike
        float vn = IZH_C;            // with p=false this acts as v_sel = C initial state
        float up = IZH_B * IZH_C;
        bool  p  = false;

        #pragma unroll 1
        for (int c = 0; c <= NCHUNK; c++) {
            if (c < NCHUNK) cp_wait1();   // oldest in-flight group (stage c) complete
            __syncthreads();              // publish x stage c cross-warp; zbuf handoff
            if (c < NCHUNK) {
                // Issue stage c+2 FIRST so the loads overlap this chunk's compute.
                const int ls = c + STAGES - 1;
                if (ls < NCHUNK) {
                    const int lslot = ls % STAGES;
                    #pragma unroll
                    for (int k = 0; k < HALF; k++)
                        cp_async16(&xring[lslot][soff + k][lane],
                                   xp + (size_t)(ls * CHUNK + soff + k) * BATCH);
                }
                cp_commit();   // empty group at the tail keeps FIFO count uniform

                const int slot = c % STAGES;
                const int cb   = c & 1;
                float4 zq;
                #pragma unroll
                for (int k = 0; k < CHUNK; k++) {
                    const float4 x = xring[slot][k][lane];
                    // input linear (frozen order)
                    const float h = w0 * x.x + w1 * x.y + w2 * x.z + w3 * x.w + bi;

                    // speculative Izhikevich step (both reset paths, select on prev p)
                    const float uB = up + IZH_D;              // == fma(z=1, D, u')
                    const float pA = izh_poly(vn, up, h);     // no-spike path (frozen)
                    const float pB = izh_poly_C(uB, h);       // spike path (folded head)
                    const float vnn  = p ? pB : pA;
                    const float usel = p ? uB : up;
                    up = usel + IZH_A * (IZH_B * vnn - usel); // frozen order
                    p  = (vnn >= IZH_VTH);
                    vn = vnn;
                    const float z = p ? 1.0f : 0.0f;

                    // pack 4 steps per STS.128 (keeps barrier STS-drain cheap)
                    if      ((k & 3) == 0) zq.x = z;
                    else if ((k & 3) == 1) zq.y = z;
                    else if ((k & 3) == 2) zq.z = z;
                    else { zq.w = z; zbuf[cb][n][k >> 2][lane] = zq; }
                }
            }
        }
    } else {
        // ───── OUTPUT warp (lags one chunk) ─────
        const float wo0 = W_out[0], wo1 = W_out[1];
        const float bo  = b_out[0];

        float vn = IZH_C;
        float up = IZH_B * IZH_C;
        bool  p  = false;
        float* op = out + elem;

        #pragma unroll 1
        for (int c = 0; c <= NCHUNK; c++) {
            __syncthreads();
            if (c > 0) {
                const int cb    = (c - 1) & 1;
                const int tbase = (c - 1) * CHUNK;
                #pragma unroll
                for (int g = 0; g < CHUNK / 4; g++) {
                    const float4 z0q = zbuf[cb][0][g][lane];
                    const float4 z1q = zbuf[cb][1][g][lane];
                    #pragma unroll
                    for (int j = 0; j < 4; j++) {
                        const float z0 = (j == 0) ? z0q.x : (j == 1) ? z0q.y : (j == 2) ? z0q.z : z0q.w;
                        const float z1 = (j == 0) ? z1q.x : (j == 1) ? z1q.y : (j == 2) ? z1q.z : z1q.w;

                        // output linear (frozen order)
                        const float y = z0 * wo0 + z1 * wo1 + bo;

                        const float uB = up + IZH_D;
                        const float pA = izh_poly(vn, up, y);
                        const float pB = izh_poly_C(uB, y);
                        const float vnn  = p ? pB : pA;
                        const float usel = p ? uB : up;
                        up = usel + IZH_A * (IZH_B * vnn - usel);
                        p  = (vnn >= IZH_VTH);
                        vn = vnn;
                        const float z2 = p ? 1.0f : 0.0f;

                        op[(size_t)(tbase + g * 4 + j) * BATCH] = z2;
                    }
                }
            }
        }
    }
}

extern "C" void kernel_launch(void* const* d_in, const int* in_sizes, int n_in,
                              void* d_out, int out_size) {
    const float4* xs    = (const float4*)d_in[0];
    const float*  W_in  = (const float*)d_in[1];
    const float*  b_in  = (const float*)d_in[2];
    const float*  W_out = (const float*)d_in[3];
    const float*  b_out = (const float*)d_in[4];
    float* out = (float*)d_out;

    dim3 grid(BATCH / EPB);   // 256 blocks
    dim3 block(TPB);          // 3 warps: hidden n0 / hidden n1 / output
    snn_izh_spec32b_kernel<<<grid, block>>>(xs, W_in, b_in, W_out, b_out, out);
}

// round 11
// speedup vs baseline: 1.0540x; 1.0540x over previous
#include <cuda_runtime.h>
#include <cuda_bf16.h>
#include <cstdint>

// Problem constants (fixed by the reference setup_inputs)
constexpr int T_STEPS = 2048;
constexpr int BATCH   = 8192;
constexpr int CHUNK   = 32;                  // timesteps per pipeline stage
constexpr int NCHUNK  = T_STEPS / CHUNK;     // 64
constexpr int STAGES  = 3;                   // x staging ring depth
constexpr int EPB     = 32;                  // elements per block
constexpr int TPB     = 128;                 // w0:hidden n0  w1:hidden n1  w2:output  w3:helper

// Izhikevich params (regular spiking)
#define IZH_A   0.02f
#define IZH_B   0.2f
#define IZH_C   (-65.0f)
#define IZH_D   8.0f
#define IZH_VTH 30.0f

// ─── dynamic smem layout (bytes) ───
constexpr int XRING_B = STAGES * CHUNK * EPB * 16;          // 49152: [STAGES][CHUNK][EPB] float4
constexpr int HBUF_B  = 2 * CHUNK * EPB * 8;                // 16384: [2][CHUNK][EPB] float2 (h0,h1)
constexpr int ZBUF_B  = 2 * 2 * (CHUNK / 4) * EPB * 16;     // 16384: [2][2][CHUNK/4][EPB] float4
constexpr int YBUF_B  = 2 * (CHUNK / 4) * EPB * 16;         //  8192: [2][CHUNK/4][EPB] float4
constexpr int SMEM_TOTAL = XRING_B + HBUF_B + ZBUF_B + YBUF_B;   // 90112

__device__ __forceinline__ void cp_async16(void* smem_dst, const void* gmem_src) {
    uint32_t s = (uint32_t)__cvta_generic_to_shared(smem_dst);
    asm volatile("cp.async.cg.shared.global [%0], [%1], 16;\n" :: "r"(s), "l"(gmem_src) : "memory");
}
__device__ __forceinline__ void cp_commit() {
    asm volatile("cp.async.commit_group;\n" ::: "memory");
}
__device__ __forceinline__ void cp_wait2() {
    asm volatile("cp.async.wait_group 2;\n" ::: "memory");
}

// The reference polynomial, FROZEN source expression (bit-exact vs reference).
__device__ __forceinline__ float izh_poly(float v, float u, float I) {
    return v + (0.04f * v * v + 5.0f * v + 140.0f - u + I);
}

__global__ __launch_bounds__(TPB) void snn_izh_helper_kernel(
    const float4* __restrict__ xs,     // [T, B] float4 (F_IN = 4)
    const float*  __restrict__ W_in,   // [2,4]
    const float*  __restrict__ b_in,   // [2]
    const float*  __restrict__ W_out,  // [1,2]
    const float*  __restrict__ b_out,  // [1]
    float*        __restrict__ out)    // [T, B]
{
    extern __shared__ char smem[];
    float4* xring = (float4*)smem;                                   // [STAGES][CHUNK][EPB]
    float2* hbuf  = (float2*)(smem + XRING_B);                       // [2][CHUNK][EPB]
    float4* zbuf  = (float4*)(smem + XRING_B + HBUF_B);              // [2][2][CHUNK/4][EPB]
    float4* ybuf  = (float4*)(smem + XRING_B + HBUF_B + ZBUF_B);     // [2][CHUNK/4][EPB]

    const int wid  = threadIdx.x >> 5;
    const int lane = threadIdx.x & 31;
    const int elem = blockIdx.x * EPB + lane;

    // Opaque C: forces the spike-path poly to compile as the same runtime
    // FMUL/FFMA/FADD sequence as the general path (proven R6 pattern).
    float Cop = IZH_C;
    asm volatile("" : "+f"(Cop));

    if (wid == 3) {
        // ───── HELPER warp: cp.async x, h-linears (chunk c), y-linear (chunk c-2) ─────
        const float w00 = W_in[0], w01 = W_in[1], w02 = W_in[2], w03 = W_in[3];
        const float w10 = W_in[4], w11 = W_in[5], w12 = W_in[6], w13 = W_in[7];
        const float bi0 = b_in[0], bi1 = b_in[1];
        const float wo0 = W_out[0], wo1 = W_out[1];
        const float bo  = b_out[0];

        const float4* xp = xs + elem;

        // prologue: stages 0,1 (2 groups)
        #pragma unroll
        for (int s = 0; s < 2; s++) {
            #pragma unroll
            for (int k = 0; k < CHUNK; k++)
                cp_async16(&xring[(s * CHUNK + k) * EPB + lane],
                           xp + (size_t)(s * CHUNK + k) * BATCH);
            cp_commit();
        }

        #pragma unroll 1
        for (int c = 0; c <= NCHUNK + 2; c++) {
            // Issue stage c+2 first (overlaps this epoch's compute)
            const int ls = c + 2;
            if (ls < NCHUNK) {
                const int lslot = ls % STAGES;
                #pragma unroll
                for (int k = 0; k < CHUNK; k++)
                    cp_async16(&xring[(lslot * CHUNK + k) * EPB + lane],
                               xp + (size_t)(ls * CHUNK + k) * BATCH);
            }
            cp_commit();   // empty groups at the tail keep the FIFO count uniform

            // y-linear for chunk c-2 (z written by hidden warps during epoch c-1)
            if (c >= 2 && c - 2 < NCHUNK) {
                const int cb2 = (c - 2) & 1;
                #pragma unroll
                for (int g = 0; g < CHUNK / 4; g++) {
                    const float4 z0q = zbuf[((cb2 * 2 + 0) * (CHUNK / 4) + g) * EPB + lane];
                    const float4 z1q = zbuf[((cb2 * 2 + 1) * (CHUNK / 4) + g) * EPB + lane];
                    float4 yq;
                    yq.x = z0q.x * wo0 + z1q.x * wo1 + bo;   // frozen order
                    yq.y = z0q.y * wo0 + z1q.y * wo1 + bo;
                    yq.z = z0q.z * wo0 + z1q.z * wo1 + bo;
                    yq.w = z0q.w * wo0 + z1q.w * wo1 + bo;
                    ybuf[(cb2 * (CHUNK / 4) + g) * EPB + lane] = yq;
                }
            }

            // h-linears for chunk c (x stage c)
            if (c < NCHUNK) {
                cp_wait2();                 // stage c complete
                const int slot = c % STAGES;
                const int hb   = c & 1;
                #pragma unroll
                for (int k = 0; k < CHUNK; k++) {
                    const float4 x = xring[(slot * CHUNK + k) * EPB + lane];
                    float2 h2;
                    h2.x = w00 * x.x + w01 * x.y + w02 * x.z + w03 * x.w + bi0;  // frozen
                    h2.y = w10 * x.x + w11 * x.y + w12 * x.z + w13 * x.w + bi1;  // frozen
                    hbuf[(hb * CHUNK + k) * EPB + lane] = h2;
                }
            }
            __syncthreads();
        }
    } else if (wid < 2) {
        // ───── HIDDEN warp (neuron n): consumes hbuf chunk c-1, produces zbuf chunk c-1 ─────
        const int n = wid;

        // speculative state: vn = pre-reset v of prev step, up = u' (pre +D), p = prev spike
        float vn = IZH_C;
        float up = IZH_B * IZH_C;
        bool  p  = false;

        #pragma unroll 1
        for (int c = 0; c <= NCHUNK + 2; c++) {
            if (c >= 1 && c <= NCHUNK) {
                const int hb = (c - 1) & 1;
                const int cb = (c - 1) & 1;
                float4 zq;
                #pragma unroll
                for (int k = 0; k < CHUNK; k++) {
                    const float2 h2 = hbuf[(hb * CHUNK + k) * EPB + lane];
                    const float h = (n == 0) ? h2.x : h2.y;

                    // speculative Izhikevich step (R6-proven exact codegen)
                    const float uB = up + IZH_D;              // == fma(z=1, D, u')
                    const float pA = izh_poly(vn,  up, h);    // no-spike path
                    const float pB = izh_poly(Cop, uB, h);    // spike path (same ops)
                    const float vnn  = p ? pB : pA;
                    const float usel = p ? uB : up;
                    up = usel + IZH_A * (IZH_B * vnn - usel); // frozen order
                    p  = (vnn >= IZH_VTH);
                    vn = vnn;
                    const float z = p ? 1.0f : 0.0f;

                    if      ((k & 3) == 0) zq.x = z;
                    else if ((k & 3) == 1) zq.y = z;
                    else if ((k & 3) == 2) zq.z = z;
                    else { zq.w = z; zbuf[((cb * 2 + n) * (CHUNK / 4) + (k >> 2)) * EPB + lane] = zq; }
                }
            }
            __syncthreads();
        }
    } else {
        // ───── OUTPUT warp: consumes ybuf chunk c-3 ─────
        float vn = IZH_C;
        float up = IZH_B * IZH_C;
        bool  p  = false;
        float* op = out + elem;

        #pragma unroll 1
        for (int c = 0; c <= NCHUNK + 2; c++) {
            if (c >= 3) {
                const int yb    = (c - 3) & 1;
                const int tbase = (c - 3) * CHUNK;
                #pragma unroll
                for (int g = 0; g < CHUNK / 4; g++) {
                    const float4 yq = ybuf[(yb * (CHUNK / 4) + g) * EPB + lane];
                    #pragma unroll
                    for (int j = 0; j < 4; j++) {
                        const float y = (j == 0) ? yq.x : (j == 1) ? yq.y : (j == 2) ? yq.z : yq.w;

                        const float uB = up + IZH_D;
                        const float pA = izh_poly(vn,  up, y);
                        const float pB = izh_poly(Cop, uB, y);
                        const float vnn  = p ? pB : pA;
                        const float usel = p ? uB : up;
                        up = usel + IZH_A * (IZH_B * vnn - usel);
                        p  = (vnn >= IZH_VTH);
                        vn = vnn;
                        const float z2 = p ? 1.0f : 0.0f;

                        op[(size_t)(tbase + g * 4 + j) * BATCH] = z2;
                    }
                }
            }
            __syncthreads();
        }
    }
}

extern "C" void kernel_launch(void* const* d_in, const int* in_sizes, int n_in,
                              void* d_out, int out_size) {
    const float4* xs    = (const float4*)d_in[0];
    const float*  W_in  = (const float*)d_in[1];
    const float*  b_in  = (const float*)d_in[2];
    const float*  W_out = (const float*)d_in[3];
    const float*  b_out = (const float*)d_in[4];
    float* out = (float*)d_out;

    static bool attr_set = false;   // idempotent host-side attribute set (no allocation)
    if (!attr_set) {
        cudaFuncSetAttribute(snn_izh_helper_kernel,
                             cudaFuncAttributeMaxDynamicSharedMemorySize, SMEM_TOTAL);
        attr_set = true;
    }

    dim3 grid(BATCH / EPB);   // 256 blocks
    dim3 block(TPB);          // 4 warps: hidden n0 / hidden n1 / output / helper
    snn_izh_helper_kernel<<<grid, block, SMEM_TOTAL>>>(xs, W_in, b_in, W_out, b_out, out);
}